// round 3
// baseline (speedup 1.0000x reference)
#include <cuda_runtime.h>
#include <cuda_bf16.h>
#include <cstdint>

// out[i, s] = sigmoid( sqrt(sum_j X[i,j]^2 * exp(lv[j])) * z[s] + sum_j X[i,j]*mu[j] )
// N = 500000 rows, D = 64, NS = 128.
//
// Persistent grid-stride version (single wave, 148*8 CTAs):
//   - half-warp per row: lanes 0-15 -> row r, 16-31 -> r+1; float4/lane = LDG.128
//   - warp processes a quad of rows per iteration (2 hoisted LDG.128, MLP=2)
//   - software pipeline: next quad's loads issued before current quad's
//     tanh/store tail, so DRAM latency is hidden by compute+stores
//   - sigmoid(a) = 0.5*tanh(a/2)+0.5 via MUFU.TANH (1 MUFU/elem)
//   - streaming cache hints: __ldcs on X (read-once), __stcs on out (write-once)

__device__ __forceinline__ float fast_tanh(float a) {
    float t;
    asm("tanh.approx.f32 %0, %1;" : "=f"(t) : "f"(a));
    return t;
}

__device__ __forceinline__ float fast_sqrt(float v) {
    float s;
    asm("sqrt.approx.f32 %0, %1;" : "=f"(s) : "f"(v));
    return s;
}

__device__ __forceinline__ void dot_pair(const float4& x, const float4& mu,
                                         const float4& ew, float& m, float& v) {
    m = x.x * mu.x;
    m = fmaf(x.y, mu.y, m);
    m = fmaf(x.z, mu.z, m);
    m = fmaf(x.w, mu.w, m);
    v = (x.x * x.x) * ew.x;
    v = fmaf(x.y * x.y, ew.y, v);
    v = fmaf(x.z * x.z, ew.z, v);
    v = fmaf(x.w * x.w, ew.w, v);
}

__device__ __forceinline__ void emit_row(float m, float v,
                                         const float4& zA, const float4& zB,
                                         float* __restrict__ orow, int hl) {
    const float sh = 0.5f * fast_sqrt(v);
    const float mh = 0.5f * m;
    float4 ra, rb;
    ra.x = fmaf(fast_tanh(fmaf(sh, zA.x, mh)), 0.5f, 0.5f);
    ra.y = fmaf(fast_tanh(fmaf(sh, zA.y, mh)), 0.5f, 0.5f);
    ra.z = fmaf(fast_tanh(fmaf(sh, zA.z, mh)), 0.5f, 0.5f);
    ra.w = fmaf(fast_tanh(fmaf(sh, zA.w, mh)), 0.5f, 0.5f);
    rb.x = fmaf(fast_tanh(fmaf(sh, zB.x, mh)), 0.5f, 0.5f);
    rb.y = fmaf(fast_tanh(fmaf(sh, zB.y, mh)), 0.5f, 0.5f);
    rb.z = fmaf(fast_tanh(fmaf(sh, zB.z, mh)), 0.5f, 0.5f);
    rb.w = fmaf(fast_tanh(fmaf(sh, zB.w, mh)), 0.5f, 0.5f);
    __stcs(reinterpret_cast<float4*>(orow) + hl, ra);
    __stcs(reinterpret_cast<float4*>(orow) + hl + 16, rb);
}

__global__ __launch_bounds__(256) void blr_sigmoid_kernel(
    const float* __restrict__ X,
    const float* __restrict__ w_mu,
    const float* __restrict__ w_lv,
    const float* __restrict__ z,
    float* __restrict__ out,
    int n)
{
    const int lane = threadIdx.x & 31;
    const int hl   = lane & 15;          // position within half-warp
    const int half = lane >> 4;          // 0 or 1: which row of the pair
    const int warp_global = (blockIdx.x * blockDim.x + threadIdx.x) >> 5;
    const int total_warps = (gridDim.x * blockDim.x) >> 5;

    // Per-lane constants (loop-invariant)
    const float4 mu4 = reinterpret_cast<const float4*>(w_mu)[hl];
    const float4 lv4 = reinterpret_cast<const float4*>(w_lv)[hl];
    const float4 ew4 = make_float4(__expf(lv4.x), __expf(lv4.y),
                                   __expf(lv4.z), __expf(lv4.w));
    const float4 zA = reinterpret_cast<const float4*>(z)[hl];
    const float4 zB = reinterpret_cast<const float4*>(z)[hl + 16];

    const int stride = total_warps * 4;  // rows per full-grid pass
    int base = warp_global * 4;          // this warp's quad: rows [base, base+4)
    if (base >= n) return;               // n % 4 == 0, quads are always complete

    // Prologue: load first quad
    float4 x0 = __ldcs(reinterpret_cast<const float4*>(X + (size_t)(base + half) * 64) + hl);
    float4 x1 = __ldcs(reinterpret_cast<const float4*>(X + (size_t)(base + 2 + half) * 64) + hl);

    while (true) {
        const int next = base + stride;

        float m0, v0, m1, v1;
        dot_pair(x0, mu4, ew4, m0, v0);
        dot_pair(x1, mu4, ew4, m1, v1);

        // Prefetch next quad before the reduce/tanh/store tail
        if (next < n) {
            x0 = __ldcs(reinterpret_cast<const float4*>(X + (size_t)(next + half) * 64) + hl);
            x1 = __ldcs(reinterpret_cast<const float4*>(X + (size_t)(next + 2 + half) * 64) + hl);
        }

        #pragma unroll
        for (int o = 8; o > 0; o >>= 1) {
            m0 += __shfl_xor_sync(0xffffffffu, m0, o);
            v0 += __shfl_xor_sync(0xffffffffu, v0, o);
            m1 += __shfl_xor_sync(0xffffffffu, m1, o);
            v1 += __shfl_xor_sync(0xffffffffu, v1, o);
        }

        emit_row(m0, v0, zA, zB, out + (size_t)(base + half) * 128, hl);
        emit_row(m1, v1, zA, zB, out + (size_t)(base + 2 + half) * 128, hl);

        if (next >= n) break;
        base = next;
    }
}

extern "C" void kernel_launch(void* const* d_in, const int* in_sizes, int n_in,
                              void* d_out, int out_size) {
    const float* X    = (const float*)d_in[0];
    const float* w_mu = (const float*)d_in[1];
    const float* w_lv = (const float*)d_in[2];
    const float* z    = (const float*)d_in[3];
    float* out = (float*)d_out;

    const int n = in_sizes[0] / 64;          // 500000 rows (divisible by 4)

    // One resident wave: 148 SMs * 8 CTAs/SM (256 thr, <=32 regs target;
    // if regs land ~40 the runtime residency is ~6 CTAs/SM, grid still one wave
    // per SM scheduler via work-stealing).
    const int blocks = 148 * 8;
    blr_sigmoid_kernel<<<blocks, 256>>>(X, w_mu, w_lv, z, out, n);
}

// round 5
// speedup vs baseline: 1.1122x; 1.1122x over previous
#include <cuda_runtime.h>
#include <cuda_bf16.h>
#include <cstdint>

// out[i, s] = sigmoid( sqrt(sum_j X[i,j]^2 * exp(lv[j])) * z[s] + sum_j X[i,j]*mu[j] )
// N = 500000 rows, D = 64, NS = 128.
//
// R2 structure (best so far): non-persistent, half-warp per row, 4 rows/warp.
//   - lane loads float4 of its row: one LDG.128 warp-instr = 2 full rows (512B)
//   - butterfly reduce over 16 lanes (offsets 8,4,2,1), 4 chains interleaved
//   - sigmoid(a) = 0.5*tanh(a/2)+0.5 via MUFU.TANH (1 MUFU/elem)
// R4 deltas vs R2 (resubmitted after infra failure):
//   - __ldcs on X (read-once) / __stcs on out (write-once): evict-first in L2,
//     keeps the 128MB read and 256MB write streams from thrashing each other
//   - 0.5 folded into per-lane z constants at setup (one fewer mul per row)
//   - regs target <=32 so occupancy stays ~8 CTA/SM

__device__ __forceinline__ float fast_tanh(float a) {
    float t;
    asm("tanh.approx.f32 %0, %1;" : "=f"(t) : "f"(a));
    return t;
}

__device__ __forceinline__ float fast_sqrt(float v) {
    float s;
    asm("sqrt.approx.f32 %0, %1;" : "=f"(s) : "f"(v));
    return s;
}

__device__ __forceinline__ void dot_pair(const float4& x, const float4& mu,
                                         const float4& ew, float& m, float& v) {
    m = x.x * mu.x;
    m = fmaf(x.y, mu.y, m);
    m = fmaf(x.z, mu.z, m);
    m = fmaf(x.w, mu.w, m);
    v = (x.x * x.x) * ew.x;
    v = fmaf(x.y * x.y, ew.y, v);
    v = fmaf(x.z * x.z, ew.z, v);
    v = fmaf(x.w * x.w, ew.w, v);
}

// zA/zB already pre-scaled by 0.5. a/2 = sqrt(v)*(0.5 z) + 0.5 m
__device__ __forceinline__ void emit_row(float m, float v,
                                         const float4& zA, const float4& zB,
                                         float* __restrict__ orow, int hl) {
    const float s  = fast_sqrt(v);
    const float mh = 0.5f * m;
    float4 ra, rb;
    ra.x = fmaf(fast_tanh(fmaf(s, zA.x, mh)), 0.5f, 0.5f);
    ra.y = fmaf(fast_tanh(fmaf(s, zA.y, mh)), 0.5f, 0.5f);
    ra.z = fmaf(fast_tanh(fmaf(s, zA.z, mh)), 0.5f, 0.5f);
    ra.w = fmaf(fast_tanh(fmaf(s, zA.w, mh)), 0.5f, 0.5f);
    rb.x = fmaf(fast_tanh(fmaf(s, zB.x, mh)), 0.5f, 0.5f);
    rb.y = fmaf(fast_tanh(fmaf(s, zB.y, mh)), 0.5f, 0.5f);
    rb.z = fmaf(fast_tanh(fmaf(s, zB.z, mh)), 0.5f, 0.5f);
    rb.w = fmaf(fast_tanh(fmaf(s, zB.w, mh)), 0.5f, 0.5f);
    __stcs(reinterpret_cast<float4*>(orow) + hl, ra);
    __stcs(reinterpret_cast<float4*>(orow) + hl + 16, rb);
}

__global__ __launch_bounds__(256) void blr_sigmoid_kernel(
    const float* __restrict__ X,
    const float* __restrict__ w_mu,
    const float* __restrict__ w_lv,
    const float* __restrict__ z,
    float* __restrict__ out,
    int n)
{
    const int lane = threadIdx.x & 31;
    const int hl   = lane & 15;          // position within half-warp
    const int half = lane >> 4;          // 0 or 1: which row of the pair
    const int warp_global = (blockIdx.x * blockDim.x + threadIdx.x) >> 5;

    // Per-lane constants
    const float4 mu4 = reinterpret_cast<const float4*>(w_mu)[hl];
    const float4 lv4 = reinterpret_cast<const float4*>(w_lv)[hl];
    const float4 ew4 = make_float4(__expf(lv4.x), __expf(lv4.y),
                                   __expf(lv4.z), __expf(lv4.w));
    float4 zA = reinterpret_cast<const float4*>(z)[hl];
    float4 zB = reinterpret_cast<const float4*>(z)[hl + 16];
    zA.x *= 0.5f; zA.y *= 0.5f; zA.z *= 0.5f; zA.w *= 0.5f;
    zB.x *= 0.5f; zB.y *= 0.5f; zB.z *= 0.5f; zB.w *= 0.5f;

    // This warp owns rows [base, base+3]; this lane's rows: base+half, base+2+half
    const int base = warp_global * 4;
    const int r0 = base + half;
    const int r1 = base + 2 + half;
    if (r0 >= n) return;
    const bool have1 = (r1 < n);

    // Hoist both loads (MLP=2), streaming policy
    float4 x0 = __ldcs(reinterpret_cast<const float4*>(X + (size_t)r0 * 64) + hl);
    float4 x1 = make_float4(0.f, 0.f, 0.f, 0.f);
    if (have1) x1 = __ldcs(reinterpret_cast<const float4*>(X + (size_t)r1 * 64) + hl);

    float m0, v0, m1, v1;
    dot_pair(x0, mu4, ew4, m0, v0);
    dot_pair(x1, mu4, ew4, m1, v1);

    // Butterfly over the 16-lane group; 4 chains interleaved for ILP
    #pragma unroll
    for (int o = 8; o > 0; o >>= 1) {
        m0 += __shfl_xor_sync(0xffffffffu, m0, o);
        v0 += __shfl_xor_sync(0xffffffffu, v0, o);
        m1 += __shfl_xor_sync(0xffffffffu, m1, o);
        v1 += __shfl_xor_sync(0xffffffffu, v1, o);
    }

    emit_row(m0, v0, zA, zB, out + (size_t)r0 * 128, hl);
    if (have1) emit_row(m1, v1, zA, zB, out + (size_t)r1 * 128, hl);
}

extern "C" void kernel_launch(void* const* d_in, const int* in_sizes, int n_in,
                              void* d_out, int out_size) {
    const float* X    = (const float*)d_in[0];
    const float* w_mu = (const float*)d_in[1];
    const float* w_lv = (const float*)d_in[2];
    const float* z    = (const float*)d_in[3];
    float* out = (float*)d_out;

    const int n = in_sizes[0] / 64;                  // 500000 rows
    const int rows_per_block = 4 * (256 / 32);       // 4 rows/warp * 8 warps
    const int blocks = (n + rows_per_block - 1) / rows_per_block;

    blr_sigmoid_kernel<<<blocks, 256>>>(X, w_mu, w_lv, z, out, n);
}